// round 1
// baseline (speedup 1.0000x reference)
#include <cuda_runtime.h>
#include <math.h>

#define S_LEN 4096
#define NBATCH 4
#define DIM 256
#define M_TOTAL (NBATCH * S_LEN)

#define QT 64           // query tile rows
#define KT 128          // key tile cols
#define QT_STRIDE 68    // padded (16B-aligned, conflict-reducing)
#define KV_STRIDE 132

// Scratch (no allocation allowed in kernel_launch)
__device__ float g_Q[M_TOTAL * DIM];
__device__ float g_K[M_TOTAL * DIM];
__device__ float g_V[M_TOTAL * DIM];
__device__ float4 g_cs[S_LEN];   // (cos0, sin0, cos1, sin1) per position

// smem layout (floats)
#define SM_QT    (256 * QT_STRIDE)        // 17408
#define SM_KVT   (KT * KV_STRIDE)         // 16896 (K chunk [64][132] or V chunk [128][132])
#define SM_PT    (KT * QT_STRIDE)         // 8704
#define SM_CSK   (KT * 4)                 // 512
#define SMEM_FLOATS (SM_QT + SM_KVT + SM_PT + SM_CSK)
#define SMEM_BYTES (SMEM_FLOATS * 4)      // 174,080 B

// ---------------------------------------------------------------------------
// 1) Per-position cos/sin table (fp64 once per launch; exact phase via int mod)
// ---------------------------------------------------------------------------
__global__ void cs_kernel() {
    int p = blockIdx.x * blockDim.x + threadIdx.x;
    if (p < S_LEN) {
        double s0, c0, s1, c1;
        sincospi(fmod((double)p, 24.0) / 12.0, &s0, &c0);    // 2*pi*p/24
        sincospi(fmod((double)p, 720.0) / 360.0, &s1, &c1);  // 2*pi*p/720
        g_cs[p] = make_float4((float)c0, (float)s0, (float)c1, (float)s1);
    }
}

// ---------------------------------------------------------------------------
// 2) QKV projection: Y = x @ W^T + b   (M=16384, N=256, K=256), z selects Q/K/V
//    Q output is pre-scaled by 1/sqrt(d) = 1/16 (bias included).
// ---------------------------------------------------------------------------
__global__ __launch_bounds__(256) void qkv_kernel(
    const float* __restrict__ x,
    const float* __restrict__ Wq, const float* __restrict__ bq,
    const float* __restrict__ Wk, const float* __restrict__ bk,
    const float* __restrict__ Wv, const float* __restrict__ bv)
{
    const float* W; const float* bias; float* out; float scale;
    int z = blockIdx.z;
    if (z == 0)      { W = Wq; bias = bq; out = g_Q; scale = 1.0f / 16.0f; }
    else if (z == 1) { W = Wk; bias = bk; out = g_K; scale = 1.0f; }
    else             { W = Wv; bias = bv; out = g_V; scale = 1.0f; }

    __shared__ float Xs[16 * 68];
    __shared__ float Ws[16 * 68];

    int tid = threadIdx.x;
    int tx = tid & 15, ty = tid >> 4;
    int m0 = blockIdx.x * 64, n0 = blockIdx.y * 64;

    float acc[4][4] = {};

    for (int k0 = 0; k0 < DIM; k0 += 16) {
        int kl = tid & 15, r = tid >> 4;
        #pragma unroll
        for (int i = 0; i < 4; i++) {
            Xs[kl * 68 + r + i * 16] = x[(m0 + r + i * 16) * DIM + k0 + kl];
            Ws[kl * 68 + r + i * 16] = W[(n0 + r + i * 16) * DIM + k0 + kl];
        }
        __syncthreads();
        #pragma unroll
        for (int kk = 0; kk < 16; kk++) {
            float4 a = *(const float4*)&Xs[kk * 68 + ty * 4];
            float4 b = *(const float4*)&Ws[kk * 68 + tx * 4];
            float av[4] = {a.x, a.y, a.z, a.w};
            float bw[4] = {b.x, b.y, b.z, b.w};
            #pragma unroll
            for (int i = 0; i < 4; i++)
                #pragma unroll
                for (int j = 0; j < 4; j++)
                    acc[i][j] += av[i] * bw[j];
        }
        __syncthreads();
    }

    int n = n0 + tx * 4;
    float bb[4] = {bias[n], bias[n + 1], bias[n + 2], bias[n + 3]};
    #pragma unroll
    for (int i = 0; i < 4; i++) {
        float4 o;
        o.x = (acc[i][0] + bb[0]) * scale;
        o.y = (acc[i][1] + bb[1]) * scale;
        o.z = (acc[i][2] + bb[2]) * scale;
        o.w = (acc[i][3] + bb[3]) * scale;
        *(float4*)&out[(m0 + ty * 4 + i) * DIM + n] = o;
    }
}

// ---------------------------------------------------------------------------
// 3) Fused flash attention with separable periodic bias.
//    Block = (batch b, 64-query tile). 256 threads (16x16).
//    S-phase: thread tile 4 rows x 8 key-cols over a 64x128 score tile.
//    PV-phase: thread tile 4 rows x 8 out-cols per 128-col chunk.
// ---------------------------------------------------------------------------
__global__ __launch_bounds__(256, 1) void attn_kernel(
    const float* __restrict__ beta, float* __restrict__ out)
{
    extern __shared__ float sm[];
    float* Qt  = sm;                 // [256][QT_STRIDE]  (d-major, transposed)
    float* KVt = Qt + SM_QT;         // K chunk [64][KV_STRIDE] or V chunk [128][KV_STRIDE]
    float* Pt  = KVt + SM_KVT;       // [KT][QT_STRIDE]   (key-major, transposed)
    float* csK = Pt + SM_PT;         // [KT][4]

    int tid = threadIdx.x;
    int tx = tid & 15, ty = tid >> 4;
    int b  = blockIdx.y;
    int q0 = blockIdx.x * QT;

    const float* Qg = g_Q + ((size_t)b * S_LEN + q0) * DIM;

    // Load Q tile transposed: Qt[k][m]
    for (int idx = tid; idx < QT * DIM; idx += 256) {
        int k = idx & 255, m = idx >> 8;
        Qt[k * QT_STRIDE + m] = Qg[m * DIM + k];
    }

    float b0 = beta[0], b1 = beta[1];
    float cr[4][4];
    #pragma unroll
    for (int i = 0; i < 4; i++) {
        float4 c = g_cs[q0 + ty * 4 + i];
        cr[i][0] = b0 * c.x; cr[i][1] = b0 * c.y;
        cr[i][2] = b1 * c.z; cr[i][3] = b1 * c.w;
    }

    float m_i[4], l_i[4];
    #pragma unroll
    for (int i = 0; i < 4; i++) { m_i[i] = -INFINITY; l_i[i] = 0.0f; }
    float o[4][16] = {};   // col = g2*128 + tx*8 + jj  ->  o[i][g2*8+jj]

    for (int t0 = 0; t0 < S_LEN; t0 += KT) {
        const float* Kg = g_K + ((size_t)b * S_LEN + t0) * DIM;
        const float* Vg = g_V + ((size_t)b * S_LEN + t0) * DIM;

        float acc[4][8] = {};

        // ---- S = Q K^T (Q already scaled by 1/sqrt(d)) ----
        #pragma unroll 1
        for (int kc = 0; kc < 4; kc++) {
            __syncthreads();
            {
                int kl = tid & 63, nb = tid >> 6;     // nb in 0..3
                #pragma unroll
                for (int ii = 0; ii < 32; ii++) {
                    int n = nb + ii * 4;
                    KVt[kl * KV_STRIDE + n] = Kg[n * DIM + kc * 64 + kl];
                }
            }
            if (kc == 0 && tid < KT) {
                float4 c = g_cs[t0 + tid];
                csK[tid * 4 + 0] = c.x; csK[tid * 4 + 1] = c.y;
                csK[tid * 4 + 2] = c.z; csK[tid * 4 + 3] = c.w;
            }
            __syncthreads();
            #pragma unroll 8
            for (int kk = 0; kk < 64; kk++) {
                float4 a  = *(const float4*)&Qt[(kc * 64 + kk) * QT_STRIDE + ty * 4];
                float4 p0 = *(const float4*)&KVt[kk * KV_STRIDE + tx * 8];
                float4 p1 = *(const float4*)&KVt[kk * KV_STRIDE + tx * 8 + 4];
                float av[4] = {a.x, a.y, a.z, a.w};
                float kv[8] = {p0.x, p0.y, p0.z, p0.w, p1.x, p1.y, p1.z, p1.w};
                #pragma unroll
                for (int i = 0; i < 4; i++)
                    #pragma unroll
                    for (int j = 0; j < 8; j++)
                        acc[i][j] += av[i] * kv[j];
            }
        }

        // ---- bias + online softmax ----
        #pragma unroll
        for (int i = 0; i < 4; i++) {
            float rm = -INFINITY;
            #pragma unroll
            for (int jj = 0; jj < 8; jj++) {
                int col = tx * 8 + jj;
                float s = acc[i][jj]
                    + cr[i][0] * csK[col * 4 + 0] + cr[i][1] * csK[col * 4 + 1]
                    + cr[i][2] * csK[col * 4 + 2] + cr[i][3] * csK[col * 4 + 3];
                acc[i][jj] = s;
                rm = fmaxf(rm, s);
            }
            #pragma unroll
            for (int msk = 1; msk < 16; msk <<= 1)
                rm = fmaxf(rm, __shfl_xor_sync(0xffffffffu, rm, msk));
            float mn = fmaxf(m_i[i], rm);
            float scale = __expf(m_i[i] - mn);
            float rs = 0.0f;
            #pragma unroll
            for (int jj = 0; jj < 8; jj++) {
                float e = __expf(acc[i][jj] - mn);
                acc[i][jj] = e;
                rs += e;
            }
            #pragma unroll
            for (int msk = 1; msk < 16; msk <<= 1)
                rs += __shfl_xor_sync(0xffffffffu, rs, msk);
            l_i[i] = l_i[i] * scale + rs;
            m_i[i] = mn;
            #pragma unroll
            for (int c = 0; c < 16; c++) o[i][c] *= scale;
        }

        // ---- store P transposed: Pt[t][r] ----
        #pragma unroll
        for (int jj = 0; jj < 8; jj++) {
            float4 v = make_float4(acc[0][jj], acc[1][jj], acc[2][jj], acc[3][jj]);
            *(float4*)&Pt[(tx * 8 + jj) * QT_STRIDE + ty * 4] = v;
        }

        // ---- O += P V (two 128-col chunks) ----
        #pragma unroll 1
        for (int g2 = 0; g2 < 2; g2++) {
            __syncthreads();   // Pt stores visible; KVt free (S-phase / prev chunk done)
            {
                int cl = tid & 127, tb = tid >> 7;   // tb in 0..1
                #pragma unroll
                for (int ii = 0; ii < 64; ii++) {
                    int t = tb + ii * 2;
                    KVt[t * KV_STRIDE + cl] = Vg[t * DIM + g2 * 128 + cl];
                }
            }
            __syncthreads();
            #pragma unroll 4
            for (int t = 0; t < KT; t++) {
                float4 p4 = *(const float4*)&Pt[t * QT_STRIDE + ty * 4];
                float4 v0 = *(const float4*)&KVt[t * KV_STRIDE + tx * 8];
                float4 v1 = *(const float4*)&KVt[t * KV_STRIDE + tx * 8 + 4];
                float pv[4] = {p4.x, p4.y, p4.z, p4.w};
                float vv[8] = {v0.x, v0.y, v0.z, v0.w, v1.x, v1.y, v1.z, v1.w};
                #pragma unroll
                for (int i = 0; i < 4; i++)
                    #pragma unroll
                    for (int jj = 0; jj < 8; jj++)
                        o[i][g2 * 8 + jj] += pv[i] * vv[jj];
            }
        }
    }

    // ---- epilogue: normalize and store ----
    float* Og = out + ((size_t)b * S_LEN + q0) * DIM;
    #pragma unroll
    for (int i = 0; i < 4; i++) {
        float inv = 1.0f / l_i[i];
        #pragma unroll
        for (int g2 = 0; g2 < 2; g2++) {
            float4 r0 = make_float4(o[i][g2*8+0]*inv, o[i][g2*8+1]*inv,
                                    o[i][g2*8+2]*inv, o[i][g2*8+3]*inv);
            float4 r1 = make_float4(o[i][g2*8+4]*inv, o[i][g2*8+5]*inv,
                                    o[i][g2*8+6]*inv, o[i][g2*8+7]*inv);
            *(float4*)&Og[(ty * 4 + i) * DIM + g2 * 128 + tx * 8]     = r0;
            *(float4*)&Og[(ty * 4 + i) * DIM + g2 * 128 + tx * 8 + 4] = r1;
        }
    }
}

// ---------------------------------------------------------------------------
extern "C" void kernel_launch(void* const* d_in, const int* in_sizes, int n_in,
                              void* d_out, int out_size)
{
    const float* x    = (const float*)d_in[0];
    const float* Wq   = (const float*)d_in[1];
    const float* bq   = (const float*)d_in[2];
    const float* Wk   = (const float*)d_in[3];
    const float* bk   = (const float*)d_in[4];
    const float* Wv   = (const float*)d_in[5];
    const float* bv   = (const float*)d_in[6];
    const float* beta = (const float*)d_in[7];
    float* out = (float*)d_out;

    (void)in_sizes; (void)n_in; (void)out_size;

    // Idempotent, deterministic, not a stream op — safe under graph capture.
    cudaFuncSetAttribute(attn_kernel, cudaFuncAttributeMaxDynamicSharedMemorySize, SMEM_BYTES);

    cs_kernel<<<16, 256>>>();
    qkv_kernel<<<dim3(M_TOTAL / 64, DIM / 64, 3), 256>>>(x, Wq, bq, Wk, bk, Wv, bv);
    attn_kernel<<<dim3(S_LEN / QT, NBATCH), 256, SMEM_BYTES>>>(beta, out);
}